// round 1
// baseline (speedup 1.0000x reference)
#include <cuda_runtime.h>
#include <cuda_bf16.h>
#include <math.h>

#define NN 50000
#define EE 800000
#define DIN 128
#define DH 64
#define DOUT 16
#define NCHUNK ((NN + 255) / 256)   // 196

// Scratch (device globals; no allocation allowed)
__device__ __align__(256) float g_h[NN * DH];
__device__ __align__(256) float g_t[NN * DH];
__device__ float g_dinv[NN];
__device__ int g_cnt[NN];
__device__ int g_rowptr[NN + 1];
__device__ int g_cursor[NN];
__device__ int g_col[EE];
__device__ int g_partial[256];

// ---------------------------------------------------------------- preprocessing
__global__ void k_zero_cnt() {
    int i = blockIdx.x * blockDim.x + threadIdx.x;
    if (i < NN) g_cnt[i] = 0;
}

__global__ void k_count(const int* __restrict__ dst) {
    int i = blockIdx.x * blockDim.x + threadIdx.x;
    if (i < EE) atomicAdd(&g_cnt[dst[i]], 1);
}

__global__ void k_dinv() {
    int i = blockIdx.x * blockDim.x + threadIdx.x;
    if (i < NN) g_dinv[i] = rsqrtf((float)(g_cnt[i] + 1));  // +1 self loop
}

// phase 1: per-chunk exclusive scan; chunk sums to g_partial
__global__ void k_scan1() {
    __shared__ int s[256];
    int tid = threadIdx.x;
    int i = blockIdx.x * 256 + tid;
    int v = (i < NN) ? g_cnt[i] : 0;
    s[tid] = v;
    __syncthreads();
#pragma unroll
    for (int o = 1; o < 256; o <<= 1) {
        int t = (tid >= o) ? s[tid - o] : 0;
        __syncthreads();
        s[tid] += t;
        __syncthreads();
    }
    int incl = s[tid];
    if (i < NN) g_rowptr[i] = incl - v;  // local exclusive
    if (tid == 255) g_partial[blockIdx.x] = incl;
}

// phase 2: scan chunk sums (single block)
__global__ void k_scan2() {
    __shared__ int s[256];
    int tid = threadIdx.x;
    int v = (tid < NCHUNK) ? g_partial[tid] : 0;
    s[tid] = v;
    __syncthreads();
#pragma unroll
    for (int o = 1; o < 256; o <<= 1) {
        int t = (tid >= o) ? s[tid - o] : 0;
        __syncthreads();
        s[tid] += t;
        __syncthreads();
    }
    g_partial[tid] = s[tid] - v;  // exclusive
}

// phase 3: add chunk offsets, init cursors
__global__ void k_scan3() {
    int i = blockIdx.x * 256 + threadIdx.x;
    if (i < NN) {
        int rp = g_rowptr[i] + g_partial[blockIdx.x];
        g_rowptr[i] = rp;
        g_cursor[i] = rp;
    }
    if (blockIdx.x == 0 && threadIdx.x == 0) g_rowptr[NN] = EE;
}

__global__ void k_fill(const int* __restrict__ src, const int* __restrict__ dst) {
    int i = blockIdx.x * blockDim.x + threadIdx.x;
    if (i < EE) {
        int d = dst[i];
        int pos = atomicAdd(&g_cursor[d], 1);
        g_col[pos] = src[i];
    }
}

// ---------------------------------------------------------------- dense GEMM [N,K]@[K,64]
template <int K>
__global__ void k_gemm(const float* __restrict__ A, const float* __restrict__ W,
                       float* __restrict__ C) {
    constexpr int PAD = 4;
    extern __shared__ float sm[];
    float* sW = sm;              // K*64
    float* sX = sm + K * 64;     // 64*(K+PAD)
    int tid = threadIdx.x;
    int base = blockIdx.x * 64;

    // load W (K*64 floats) as float4
    const float4* W4 = (const float4*)W;
    float4* sW4 = (float4*)sW;
    for (int i = tid; i < K * 16; i += 256) sW4[i] = W4[i];

    // load X tile (64 rows x K) as float4
    for (int i = tid; i < 64 * (K / 4); i += 256) {
        int r = i / (K / 4), kk = i % (K / 4);
        float4 v = make_float4(0.f, 0.f, 0.f, 0.f);
        if (base + r < NN) v = *(const float4*)(A + (size_t)(base + r) * K + kk * 4);
        *(float4*)(sX + r * (K + PAD) + kk * 4) = v;
    }
    __syncthreads();

    int tx = tid & 15, ty = tid >> 4;  // 16 col-groups x 16 row-groups
    float acc[4][4];
#pragma unroll
    for (int i = 0; i < 4; i++)
#pragma unroll
        for (int j = 0; j < 4; j++) acc[i][j] = 0.f;

#pragma unroll 4
    for (int k = 0; k < K; k++) {
        float4 wv = *(const float4*)(sW + k * 64 + tx * 4);
#pragma unroll
        for (int i = 0; i < 4; i++) {
            float a = sX[(ty * 4 + i) * (K + PAD) + k];
            acc[i][0] = fmaf(a, wv.x, acc[i][0]);
            acc[i][1] = fmaf(a, wv.y, acc[i][1]);
            acc[i][2] = fmaf(a, wv.z, acc[i][2]);
            acc[i][3] = fmaf(a, wv.w, acc[i][3]);
        }
    }
#pragma unroll
    for (int i = 0; i < 4; i++) {
        int r = base + ty * 4 + i;
        if (r < NN)
            *(float4*)(C + (size_t)r * DH + tx * 4) =
                make_float4(acc[i][0], acc[i][1], acc[i][2], acc[i][3]);
    }
}

// ------------------------------------------------------- aggregation + bias + ELU
// 64 threads per node (one per feature column), 4 nodes per block
__global__ void k_agg(const float* __restrict__ hin, float* __restrict__ hout,
                      const float* __restrict__ b) {
    int t = threadIdx.x;
    int node = blockIdx.x * 4 + threadIdx.y;
    if (node >= NN) return;
    float dd = g_dinv[node];
    int beg = g_rowptr[node], end = g_rowptr[node + 1];
    float acc = hin[(size_t)node * DH + t] * dd * dd;  // self loop
    int k = beg;
    for (; k + 1 < end; k += 2) {
        int j0 = g_col[k];
        int j1 = g_col[k + 1];
        float n0 = g_dinv[j0] * dd;
        float n1 = g_dinv[j1] * dd;
        float h0 = hin[(size_t)j0 * DH + t];
        float h1 = hin[(size_t)j1 * DH + t];
        acc = fmaf(h0, n0, acc);
        acc = fmaf(h1, n1, acc);
    }
    if (k < end) {
        int j = g_col[k];
        acc = fmaf(hin[(size_t)j * DH + t], g_dinv[j] * dd, acc);
    }
    acc += b[t];
    hout[(size_t)node * DH + t] = (acc > 0.f) ? acc : expm1f(acc);
}

// ------------------------------------------------------- FC + softmax (warp per node)
__global__ void k_fc(const float* __restrict__ h, const float* __restrict__ fw,
                     const float* __restrict__ fb, float* __restrict__ out) {
    __shared__ float sW[DH * DOUT];
    __shared__ float sh[4][DH];
    for (int i = threadIdx.x; i < DH * DOUT; i += 128) sW[i] = fw[i];
    __syncthreads();
    int warp = threadIdx.x >> 5, lane = threadIdx.x & 31;
    int node = blockIdx.x * 4 + warp;
    if (node >= NN) return;
    sh[warp][lane] = h[(size_t)node * DH + lane];
    sh[warp][lane + 32] = h[(size_t)node * DH + lane + 32];
    __syncwarp();
    float v = 0.f;
    if (lane < DOUT) {
        v = fb[lane];
#pragma unroll
        for (int kk = 0; kk < DH; kk++) v = fmaf(sh[warp][kk], sW[kk * DOUT + lane], v);
    }
    // softmax over 16 lanes (all of lanes 0..15 hold valid logits)
    float m = v;
#pragma unroll
    for (int o = 8; o; o >>= 1) m = fmaxf(m, __shfl_xor_sync(0xffffffffu, m, o, 16));
    float e = (lane < DOUT) ? expf(v - m) : 0.f;
    float s = e;
#pragma unroll
    for (int o = 8; o; o >>= 1) s += __shfl_xor_sync(0xffffffffu, s, o, 16);
    if (lane < DOUT) out[(size_t)node * DOUT + lane] = e / s;
}

// ---------------------------------------------------------------- launch
extern "C" void kernel_launch(void* const* d_in, const int* in_sizes, int n_in,
                              void* d_out, int out_size) {
    const float* x = (const float*)d_in[0];
    const int* ei = (const int*)d_in[1];   // [2, E] row-major
    const float* w0 = (const float*)d_in[2];
    const float* b0 = (const float*)d_in[3];
    const float* w1 = (const float*)d_in[4];
    const float* b1 = (const float*)d_in[5];
    const float* w2 = (const float*)d_in[6];
    const float* b2 = (const float*)d_in[7];
    const float* fw = (const float*)d_in[8];
    const float* fb = (const float*)d_in[9];
    float* out = (float*)d_out;
    const int* src = ei;
    const int* dst = ei + EE;

    float *p_h, *p_t;
    cudaGetSymbolAddress((void**)&p_h, g_h);
    cudaGetSymbolAddress((void**)&p_t, g_t);

    const int smem128 = (128 * 64 + 64 * (128 + 4)) * 4;  // 66560 B
    const int smem64 = (64 * 64 + 64 * (64 + 4)) * 4;     // 33792 B
    cudaFuncSetAttribute(k_gemm<128>, cudaFuncAttributeMaxDynamicSharedMemorySize, smem128);
    cudaFuncSetAttribute(k_gemm<64>, cudaFuncAttributeMaxDynamicSharedMemorySize, smem64);

    // preprocessing
    k_zero_cnt<<<(NN + 255) / 256, 256>>>();
    k_count<<<(EE + 255) / 256, 256>>>(dst);
    k_dinv<<<(NN + 255) / 256, 256>>>();
    k_scan1<<<NCHUNK, 256>>>();
    k_scan2<<<1, 256>>>();
    k_scan3<<<NCHUNK, 256>>>();
    k_fill<<<(EE + 255) / 256, 256>>>(src, dst);

    const int gemm_grid = (NN + 63) / 64;
    const dim3 agg_block(64, 4);
    const int agg_grid = (NN + 3) / 4;

    // layer 0
    k_gemm<128><<<gemm_grid, 256, smem128>>>(x, w0, p_t);
    k_agg<<<agg_grid, agg_block>>>(p_t, p_h, b0);
    // layer 1
    k_gemm<64><<<gemm_grid, 256, smem64>>>(p_h, w1, p_t);
    k_agg<<<agg_grid, agg_block>>>(p_t, p_h, b1);
    // layer 2
    k_gemm<64><<<gemm_grid, 256, smem64>>>(p_h, w2, p_t);
    k_agg<<<agg_grid, agg_block>>>(p_t, p_h, b2);
    // head
    k_fc<<<(NN + 3) / 4, 128>>>(p_h, fw, fb, out);
}

// round 2
// speedup vs baseline: 1.2768x; 1.2768x over previous
#include <cuda_runtime.h>
#include <cuda_bf16.h>
#include <math.h>

#define NN 50000
#define EE 800000
#define DIN 128
#define DH 64
#define DOUT 16
#define NCHUNK ((NN + 255) / 256)   // 196
#define EBLK ((EE + 255) / 256)     // 3125

// Scratch (device globals; no allocation allowed)
__device__ __align__(256) float g_h[NN * DH];
__device__ __align__(256) float g_t[NN * DH];
__device__ float g_dinv[NN];
__device__ int g_cnt[NN];
__device__ int g_lexcl[NN];          // chunk-local exclusive scan of cnt
__device__ int g_rowptr[NN + 1];
__device__ int g_loc[EE];            // per-edge slot within its dst row
__device__ int g_col[EE];
__device__ int g_choff[256];         // exclusive chunk offsets

// ---------------------------------------------------------------- preprocessing
__global__ void k_zero_cnt() {
    int i = blockIdx.x * blockDim.x + threadIdx.x;
    if (i < NN) g_cnt[i] = 0;
}

// count degrees AND record each edge's local slot -> later non-atomic scatter
__global__ void k_count(const int* __restrict__ dst) {
    int i = blockIdx.x * blockDim.x + threadIdx.x;
    if (i < EE) g_loc[i] = atomicAdd(&g_cnt[dst[i]], 1);
}

// per-chunk scan (warp shuffles) + dinv computation fused in
__global__ void k_scan1() {
    __shared__ int wsum[8];
    int tid = threadIdx.x;
    int i = blockIdx.x * 256 + tid;
    int v = (i < NN) ? g_cnt[i] : 0;
    if (i < NN) g_dinv[i] = rsqrtf((float)(v + 1));  // +1 self loop
    int lane = tid & 31, w = tid >> 5;
    int incl = v;
#pragma unroll
    for (int o = 1; o < 32; o <<= 1) {
        int t = __shfl_up_sync(0xffffffffu, incl, o);
        if (lane >= o) incl += t;
    }
    if (lane == 31) wsum[w] = incl;
    __syncthreads();
    if (w == 0) {
        int s = (lane < 8) ? wsum[lane] : 0;
#pragma unroll
        for (int o = 1; o < 8; o <<= 1) {
            int t = __shfl_up_sync(0xffffffffu, s, o);
            if (lane >= o) s += t;
        }
        if (lane < 8) wsum[lane] = s;  // inclusive warp sums
    }
    __syncthreads();
    int woff = (w > 0) ? wsum[w - 1] : 0;
    if (i < NN) g_lexcl[i] = woff + incl - v;
    if (tid == 255) g_choff[blockIdx.x] = woff + incl;  // chunk total (scanned next)
}

// scan the 196 chunk totals -> exclusive chunk offsets
__global__ void k_scan2() {
    __shared__ int wsum[8];
    int tid = threadIdx.x;
    int v = (tid < NCHUNK) ? g_choff[tid] : 0;
    int lane = tid & 31, w = tid >> 5;
    int incl = v;
#pragma unroll
    for (int o = 1; o < 32; o <<= 1) {
        int t = __shfl_up_sync(0xffffffffu, incl, o);
        if (lane >= o) incl += t;
    }
    if (lane == 31) wsum[w] = incl;
    __syncthreads();
    if (w == 0) {
        int s = (lane < 8) ? wsum[lane] : 0;
#pragma unroll
        for (int o = 1; o < 8; o <<= 1) {
            int t = __shfl_up_sync(0xffffffffu, s, o);
            if (lane >= o) s += t;
        }
        if (lane < 8) wsum[lane] = s;
    }
    __syncthreads();
    int woff = (w > 0) ? wsum[w - 1] : 0;
    g_choff[tid] = woff + incl - v;  // exclusive
}

// fused: finalize rowptr (blocks [0,NCHUNK)) + non-atomic CSR scatter (rest)
__global__ void k_finish(const int* __restrict__ src, const int* __restrict__ dst) {
    int b = blockIdx.x;
    if (b < NCHUNK) {
        int i = b * 256 + threadIdx.x;
        if (i < NN) g_rowptr[i] = g_lexcl[i] + g_choff[b];
        if (b == 0 && threadIdx.x == 0) g_rowptr[NN] = EE;
    } else {
        int i = (b - NCHUNK) * 256 + threadIdx.x;
        if (i < EE) {
            int d = dst[i];
            g_col[g_lexcl[d] + g_choff[d >> 8] + g_loc[i]] = src[i];
        }
    }
}

// ---------------------------------------------------------------- dense GEMM [N,K]@[K,64]
template <int K>
__global__ void k_gemm(const float* __restrict__ A, const float* __restrict__ W,
                       float* __restrict__ C) {
    constexpr int PAD = 4;
    extern __shared__ float sm[];
    float* sW = sm;              // K*64
    float* sX = sm + K * 64;     // 64*(K+PAD)
    int tid = threadIdx.x;
    int base = blockIdx.x * 64;

    const float4* W4 = (const float4*)W;
    float4* sW4 = (float4*)sW;
    for (int i = tid; i < K * 16; i += 256) sW4[i] = W4[i];

    for (int i = tid; i < 64 * (K / 4); i += 256) {
        int r = i / (K / 4), kk = i % (K / 4);
        float4 v = make_float4(0.f, 0.f, 0.f, 0.f);
        if (base + r < NN) v = *(const float4*)(A + (size_t)(base + r) * K + kk * 4);
        *(float4*)(sX + r * (K + PAD) + kk * 4) = v;
    }
    __syncthreads();

    int tx = tid & 15, ty = tid >> 4;
    float acc[4][4];
#pragma unroll
    for (int i = 0; i < 4; i++)
#pragma unroll
        for (int j = 0; j < 4; j++) acc[i][j] = 0.f;

#pragma unroll 4
    for (int k = 0; k < K; k++) {
        float4 wv = *(const float4*)(sW + k * 64 + tx * 4);
#pragma unroll
        for (int i = 0; i < 4; i++) {
            float a = sX[(ty * 4 + i) * (K + PAD) + k];
            acc[i][0] = fmaf(a, wv.x, acc[i][0]);
            acc[i][1] = fmaf(a, wv.y, acc[i][1]);
            acc[i][2] = fmaf(a, wv.z, acc[i][2]);
            acc[i][3] = fmaf(a, wv.w, acc[i][3]);
        }
    }
#pragma unroll
    for (int i = 0; i < 4; i++) {
        int r = base + ty * 4 + i;
        if (r < NN)
            *(float4*)(C + (size_t)r * DH + tx * 4) =
                make_float4(acc[i][0], acc[i][1], acc[i][2], acc[i][3]);
    }
}

// ------------------------------------------------------- aggregation + bias + ELU
// float2 per thread: 32 threads per node, 8 nodes per 256-thread block, 4-edge unroll
__global__ void k_agg(const float2* __restrict__ hin, float2* __restrict__ hout,
                      const float* __restrict__ bias) {
    int lane = threadIdx.x;               // 0..31 -> feature pair
    int node = blockIdx.x * 8 + threadIdx.y;
    if (node >= NN) return;
    float dd = g_dinv[node];
    int beg = g_rowptr[node], end = g_rowptr[node + 1];
    float2 hv = hin[(size_t)node * 32 + lane];
    float2 acc = make_float2(hv.x * dd * dd, hv.y * dd * dd);  // self loop
    int k = beg;
    for (; k + 4 <= end; k += 4) {
        int j0 = g_col[k], j1 = g_col[k + 1], j2 = g_col[k + 2], j3 = g_col[k + 3];
        float n0 = g_dinv[j0] * dd, n1 = g_dinv[j1] * dd;
        float n2 = g_dinv[j2] * dd, n3 = g_dinv[j3] * dd;
        float2 h0 = hin[(size_t)j0 * 32 + lane];
        float2 h1 = hin[(size_t)j1 * 32 + lane];
        float2 h2 = hin[(size_t)j2 * 32 + lane];
        float2 h3 = hin[(size_t)j3 * 32 + lane];
        acc.x = fmaf(h0.x, n0, acc.x); acc.y = fmaf(h0.y, n0, acc.y);
        acc.x = fmaf(h1.x, n1, acc.x); acc.y = fmaf(h1.y, n1, acc.y);
        acc.x = fmaf(h2.x, n2, acc.x); acc.y = fmaf(h2.y, n2, acc.y);
        acc.x = fmaf(h3.x, n3, acc.x); acc.y = fmaf(h3.y, n3, acc.y);
    }
    for (; k < end; k++) {
        int j = g_col[k];
        float n = g_dinv[j] * dd;
        float2 h = hin[(size_t)j * 32 + lane];
        acc.x = fmaf(h.x, n, acc.x);
        acc.y = fmaf(h.y, n, acc.y);
    }
    float2 bb = ((const float2*)bias)[lane];
    acc.x += bb.x;
    acc.y += bb.y;
    acc.x = (acc.x > 0.f) ? acc.x : expm1f(acc.x);
    acc.y = (acc.y > 0.f) ? acc.y : expm1f(acc.y);
    hout[(size_t)node * 32 + lane] = acc;
}

// ------------------------------------------------------- FC + softmax (warp per node)
__global__ void k_fc(const float* __restrict__ h, const float* __restrict__ fw,
                     const float* __restrict__ fb, float* __restrict__ out) {
    __shared__ float sW[DH * DOUT];
    __shared__ float sh[8][DH];
    for (int i = threadIdx.x; i < DH * DOUT; i += 256) sW[i] = fw[i];
    __syncthreads();
    int warp = threadIdx.x >> 5, lane = threadIdx.x & 31;
    int node = blockIdx.x * 8 + warp;
    if (node >= NN) return;
    sh[warp][lane] = h[(size_t)node * DH + lane];
    sh[warp][lane + 32] = h[(size_t)node * DH + lane + 32];
    __syncwarp();
    float v = 0.f;
    if (lane < DOUT) {
        v = fb[lane];
#pragma unroll
        for (int kk = 0; kk < DH; kk++) v = fmaf(sh[warp][kk], sW[kk * DOUT + lane], v);
    }
    float m = v;
#pragma unroll
    for (int o = 8; o; o >>= 1) m = fmaxf(m, __shfl_xor_sync(0xffffffffu, m, o, 16));
    float e = (lane < DOUT) ? expf(v - m) : 0.f;
    float s = e;
#pragma unroll
    for (int o = 8; o; o >>= 1) s += __shfl_xor_sync(0xffffffffu, s, o, 16);
    if (lane < DOUT) out[(size_t)node * DOUT + lane] = e / s;
}

// ---------------------------------------------------------------- launch
extern "C" void kernel_launch(void* const* d_in, const int* in_sizes, int n_in,
                              void* d_out, int out_size) {
    const float* x = (const float*)d_in[0];
    const int* ei = (const int*)d_in[1];   // [2, E] row-major
    const float* w0 = (const float*)d_in[2];
    const float* b0 = (const float*)d_in[3];
    const float* w1 = (const float*)d_in[4];
    const float* b1 = (const float*)d_in[5];
    const float* w2 = (const float*)d_in[6];
    const float* b2 = (const float*)d_in[7];
    const float* fw = (const float*)d_in[8];
    const float* fb = (const float*)d_in[9];
    float* out = (float*)d_out;
    const int* src = ei;
    const int* dst = ei + EE;

    float *p_h, *p_t;
    cudaGetSymbolAddress((void**)&p_h, g_h);
    cudaGetSymbolAddress((void**)&p_t, g_t);

    const int smem128 = (128 * 64 + 64 * (128 + 4)) * 4;  // 66560 B
    const int smem64 = (64 * 64 + 64 * (64 + 4)) * 4;     // 33792 B
    cudaFuncSetAttribute(k_gemm<128>, cudaFuncAttributeMaxDynamicSharedMemorySize, smem128);
    cudaFuncSetAttribute(k_gemm<64>, cudaFuncAttributeMaxDynamicSharedMemorySize, smem64);

    // preprocessing (5 kernels)
    k_zero_cnt<<<NCHUNK, 256>>>();
    k_count<<<EBLK, 256>>>(dst);
    k_scan1<<<NCHUNK, 256>>>();
    k_scan2<<<1, 256>>>();
    k_finish<<<NCHUNK + EBLK, 256>>>(src, dst);

    const int gemm_grid = (NN + 63) / 64;
    const dim3 agg_block(32, 8);
    const int agg_grid = (NN + 7) / 8;

    // layer 0
    k_gemm<128><<<gemm_grid, 256, smem128>>>(x, w0, p_t);
    k_agg<<<agg_grid, agg_block>>>((const float2*)p_t, (float2*)p_h, b0);
    // layer 1
    k_gemm<64><<<gemm_grid, 256, smem64>>>(p_h, w1, p_t);
    k_agg<<<agg_grid, agg_block>>>((const float2*)p_t, (float2*)p_h, b1);
    // layer 2
    k_gemm<64><<<gemm_grid, 256, smem64>>>(p_h, w2, p_t);
    k_agg<<<agg_grid, agg_block>>>((const float2*)p_t, (float2*)p_h, b2);
    // head
    k_fc<<<(NN + 7) / 8, 256>>>(p_h, fw, fb, out);
}